// round 15
// baseline (speedup 1.0000x reference)
#include <cuda_runtime.h>
#include <cstdint>
#include <cstddef>

#define K3   27
#define PPK  131072
#define NVOX 262144
#define CIN  32
#define COUT 32
#define TPB  128
#define SUB  128      // pairs per subtile
#define NSUB 4
#define TILE (SUB * NSUB)   // 512 pairs per block
#define BIAS_BLOCKS 8192    // NVOX*8/256

// Pre-built fp16 mma B fragments: [ko][ng][lane] = {b0_kg0, b1_kg0, b0_kg1, b1_kg1}
__device__ __align__(16) uint4 Wfrag16[K3 * 4 * 32];

// ---------- helpers ----------
// pack (a,b) -> f16x2, a in LOW half
__device__ __forceinline__ unsigned pk_f16(float a, float b) {
    unsigned r;
    asm("cvt.rn.f16x2.f32 %0, %1, %2;" : "=r"(r) : "f"(b), "f"(a));
    return r;
}
__device__ __forceinline__ void red4(float* p, float a, float b, float c, float d) {
    asm volatile("red.global.add.v4.f32 [%0], {%1, %2, %3, %4};"
                 :: "l"(p), "f"(a), "f"(b), "f"(c), "f"(d) : "memory");
}
__device__ __forceinline__ void ldsm4(unsigned &r0, unsigned &r1, unsigned &r2, unsigned &r3,
                                      unsigned addr) {
    asm volatile("ldmatrix.sync.aligned.m8n8.x4.shared.b16 {%0,%1,%2,%3}, [%4];"
                 : "=r"(r0), "=r"(r1), "=r"(r2), "=r"(r3) : "r"(addr));
}
__device__ __forceinline__ void mma_f16(float c[4],
                                        unsigned a0, unsigned a1, unsigned a2, unsigned a3,
                                        unsigned b0, unsigned b1) {
    asm volatile(
        "mma.sync.aligned.m16n8k16.row.col.f32.f16.f16.f32 "
        "{%0,%1,%2,%3}, {%4,%5,%6,%7}, {%8,%9}, {%0,%1,%2,%3};"
        : "+f"(c[0]), "+f"(c[1]), "+f"(c[2]), "+f"(c[3])
        : "r"(a0), "r"(a1), "r"(a2), "r"(a3), "r"(b0), "r"(b1));
}
__device__ __forceinline__ unsigned smem_u32(const void* p) {
    unsigned a;
    asm("{ .reg .u64 t; cvta.to.shared.u64 t, %1; cvt.u32.u64 %0, t; }" : "=r"(a) : "l"(p));
    return a;
}

// A tile addressing: logical row r (0..127) = 64B, packed 2 rows per 128B phys row.
// granule slot g (0..3, 16B each) swizzled by (r>>1)&3.
__device__ __forceinline__ unsigned a_addr(int r, int g) {
    return (unsigned)(((r >> 1) * 128) + ((r & 1) * 64) + ((g ^ ((r >> 1) & 3)) << 4));
}

// ---------- merged prep: bias init + W fp16 fragment build ----------
__global__ __launch_bounds__(256) void prep_kernel(
    const float* __restrict__ Wg, const float* __restrict__ bias,
    float4* __restrict__ out) {
    const int bid = blockIdx.x;
    const int t = threadIdx.x;
    if (bid < BIAS_BLOCKS) {
        int idx = bid * 256 + t;
        float4 b = __ldg(((const float4*)bias) + (idx & 7));
        out[idx] = b;
        return;
    }
    const int ko = bid - BIAS_BLOCKS;
    const float* w = Wg + ko * 1024;
    if (t < 128) {
        int ng = t >> 5, lane = t & 31;
        int q = lane & 3;
        int n = ng * 8 + (lane >> 2);
        unsigned b[4];
#pragma unroll
        for (int kg = 0; kg < 2; kg++) {
            int k0 = kg * 16 + q * 2;
            b[2 * kg + 0] = pk_f16(__ldg(w + (k0 + 0) * 32 + n), __ldg(w + (k0 + 1) * 32 + n));
            b[2 * kg + 1] = pk_f16(__ldg(w + (k0 + 8) * 32 + n), __ldg(w + (k0 + 9) * 32 + n));
        }
        Wfrag16[(ko * 4 + ng) * 32 + lane] = make_uint4(b[0], b[1], b[2], b[3]);
    }
}

// ---------- per-subtile compute + scatter (C staged in dedicated warp-private buf) ----------
__device__ __forceinline__ void compute_tile(
    char* A, char* C_s, const int* dst_s, const uint4 bf[4],
    float* __restrict__ out, int lane, int wid) {

    const unsigned asb = smem_u32(A);
    const int mrow = ((lane >> 3) & 1) * 8 + (lane & 7);
    const int csel = lane >> 4;
    const int qr = lane >> 2;
    const int qq = lane & 3;
    const int wbase = wid * 32;
    char* Cw = C_s + wid * 2048;         // 16 phys rows x 128B, warp-private

#pragma unroll
    for (int mg = 0; mg < 2; mg++) {
        const int mgbase = wbase + mg * 16;
        const int row = mgbase + mrow;

        // A fragments for this mg only
        unsigned af[2][4];
#pragma unroll
        for (int kg = 0; kg < 2; kg++)
            ldsm4(af[kg][0], af[kg][1], af[kg][2], af[kg][3],
                  asb + a_addr(row, kg * 2 + csel));

        // 8 MMAs
        float c[4][4];
#pragma unroll
        for (int ng = 0; ng < 4; ng++) {
#pragma unroll
            for (int i = 0; i < 4; i++) c[ng][i] = 0.0f;
            mma_f16(c[ng], af[0][0], af[0][1], af[0][2], af[0][3], bf[ng].x, bf[ng].y);
            mma_f16(c[ng], af[1][0], af[1][1], af[1][2], af[1][3], bf[ng].z, bf[ng].w);
        }

        // stage C (warp-private region; prior scatter by this warp already done)
#pragma unroll
        for (int ng = 0; ng < 4; ng++) {
            int chunk = ng * 2 + (qq >> 1);
            int sub = (qq & 1) * 8;
            *(float2*)(Cw + qr * 128 + ((chunk ^ qr) << 4) + sub) =
                make_float2(c[ng][0], c[ng][1]);
            *(float2*)(Cw + (qr + 8) * 128 + ((chunk ^ qr) << 4) + sub) =
                make_float2(c[ng][2], c[ng][3]);
        }
        __syncwarp();

        // coalesced scatter: 8 lanes cover one 128B dst row
#pragma unroll
        for (int j = 0; j < 4; j++) {
            int idx = j * 32 + lane;     // 128 = 16 rows x 8 chunks
            int lr = idx >> 3;
            int q = idx & 7;
            int cc = q ^ (lr & 7);
            float4 v = *(const float4*)(Cw + lr * 128 + q * 16);
            red4(out + (size_t)dst_s[mgbase + lr] * COUT + cc * 4, v.x, v.y, v.z, v.w);
        }
        __syncwarp();
    }
}

// ---------- main conv: four pipelined 128-pair subtiles per block ----------
__global__ __launch_bounds__(TPB, 6) void conv_f16_kernel(
    const float4* __restrict__ in_f4,
    const int2*   __restrict__ nbmap2,
    float*        __restrict__ out) {

    __shared__ __align__(128) char A_s[2][64 * 128];  // 2 x 8KB f16 tiles
    __shared__ __align__(128) char C_s[4 * 2048];     // 8KB warp-private C staging
    __shared__ int src_s[TILE];
    __shared__ int dst_s[TILE];

    const int t = threadIdx.x;
    const int lane = t & 31;
    const int wid = t >> 5;
    const int ko = blockIdx.y;
    const long base = (long)ko * PPK + (long)blockIdx.x * TILE;

    // nbmap for all 4 subtiles
#pragma unroll
    for (int j = 0; j < NSUB; j++) {
        int2 a = __ldg(nbmap2 + base + j * TPB + t);
        src_s[j * TPB + t] = a.x;
        dst_s[j * TPB + t] = a.y;
    }

    // W fragments (registers for whole kernel)
    uint4 bf[4];
#pragma unroll
    for (int ng = 0; ng < 4; ng++)
        bf[ng] = __ldg(&Wfrag16[(ko * 4 + ng) * 32 + lane]);
    __syncthreads();

    // ---- gather subtile 0 -> A[0] ----
#pragma unroll
    for (int j = 0; j < 8; j++) {
        int idx = j * TPB + t;
        int r = idx >> 3;
        int c = idx & 7;
        float4 v = __ldg(in_f4 + (size_t)src_s[r] * 8 + c);
        *(uint2*)(A_s[0] + a_addr(r, c >> 1) + (c & 1) * 8) =
            make_uint2(pk_f16(v.x, v.y), pk_f16(v.z, v.w));
    }
    // ---- prefetch subtile 1 ----
    float4 g[8];
#pragma unroll
    for (int j = 0; j < 8; j++) {
        int idx = j * TPB + t;
        int r = SUB + (idx >> 3);
        int c = idx & 7;
        g[j] = __ldg(in_f4 + (size_t)src_s[r] * 8 + c);
    }
    __syncthreads();

    // ---- pipeline: compute_s | store_{s+1} | prefetch_{s+2} | sync ----
#pragma unroll
    for (int s = 0; s < NSUB; s++) {
        compute_tile(A_s[s & 1], C_s, dst_s + s * SUB, bf, out, lane, wid);

        if (s < NSUB - 1) {
            // store prefetched subtile s+1 -> other A buffer
            char* An = A_s[(s + 1) & 1];
#pragma unroll
            for (int j = 0; j < 8; j++) {
                int idx = j * TPB + t;
                int r = idx >> 3;
                int c = idx & 7;
                *(uint2*)(An + a_addr(r, c >> 1) + (c & 1) * 8) =
                    make_uint2(pk_f16(g[j].x, g[j].y), pk_f16(g[j].z, g[j].w));
            }
            // prefetch subtile s+2
            if (s < NSUB - 2) {
#pragma unroll
                for (int j = 0; j < 8; j++) {
                    int idx = j * TPB + t;
                    int r = (s + 2) * SUB + (idx >> 3);
                    int c = idx & 7;
                    g[j] = __ldg(in_f4 + (size_t)src_s[r] * 8 + c);
                }
            }
            __syncthreads();
        }
    }
}

extern "C" void kernel_launch(void* const* d_in, const int* in_sizes, int n_in,
                              void* d_out, int out_size) {
    const float* in_f  = (const float*)d_in[0];   // [262144, 32] f32
    const float* W     = (const float*)d_in[1];   // [27, 32, 32] f32
    const float* bias  = (const float*)d_in[2];   // [32] f32
    const int*   nbmap = (const int*)d_in[3];     // [M, 2] i32
    float*       out   = (float*)d_out;           // [262144, 32] f32
    (void)in_sizes; (void)n_in; (void)out_size;

    prep_kernel<<<BIAS_BLOCKS + K3, 256>>>(W, bias, (float4*)out);

    dim3 grid(PPK / TILE, K3);
    conv_f16_kernel<<<grid, TPB>>>((const float4*)in_f, (const int2*)nbmap, out);
}